// round 13
// baseline (speedup 1.0000x reference)
#include <cuda_runtime.h>
#include <math_constants.h>

#define N 512
#define D 128
#define MARGIN 0.3f
#define APB 4            // anchors per block
#define NBLK (N / APB)   // 128 blocks = one wave
#define TPB 512          // thread t owns row j = t
#define NF4 (D / 4)      // 32 float4 per row
#define SMEM_DYN (N * 32 * 4)   // 512 rows x 32 floats per col-tile = 64KB

__device__ double       g_sum  = 0.0;
__device__ int          g_cnt  = 0;
__device__ unsigned int g_done = 0u;

__global__ __launch_bounds__(TPB)
void triplet_onekernel(const float* __restrict__ X,
                       const int* __restrict__ labels,
                       float* __restrict__ out)
{
    // sX[r][slot], slot = c ^ (r & 31): word-level swizzle, conflict-free for
    // both the coalesced staging STS.32 and the row-private compute LDS.32.
    extern __shared__ __align__(16) float sX[];

    __shared__ float4 sA4[APB][NF4];   // 4 anchor rows
    __shared__ float  sna[APB];        // anchor squared norms
    __shared__ int    slbl[N];
    __shared__ int    npos[APB];
    __shared__ float  posA[APB][64];
    __shared__ float  wsum[16];
    __shared__ int    wcnt[16];

    const int tid  = threadIdx.x;
    const int lane = tid & 31;
    const int warp = tid >> 5;
    const int i0   = blockIdx.x * APB;

    slbl[tid] = labels[tid];
    if (tid < APB) npos[tid] = 0;

    // anchors -> smem (warp a loads anchor a; one float4 per lane)
    if (warp < APB)
        sA4[warp][lane] = ((const float4*)(X + (i0 + warp) * D))[lane];

    // Staging geometry (constant across tiles):
    // idx = v*512 + tid; r = idx>>3 (row), f = idx&7 (float4-in-tile).
    // lanes 0-7 share r -> one 128B line per 8 lanes (coalesced LDG.128).
    const float4* __restrict__ X4 = (const float4*)X;
    int gofs[8], sbase[8], skey[8];
    #pragma unroll
    for (int v = 0; v < 8; v++) {
        const int idx = v * TPB + tid;
        const int r = idx >> 3, f = idx & 7;
        gofs[v]  = r * NF4 + f;          // + t*8 per tile
        sbase[v] = r * 32 + 4 * f;       // word base before xor
        skey[v]  = r & 31;               // swizzle key
    }

    // prefetch tile 0
    float4 pf[8];
    #pragma unroll
    for (int v = 0; v < 8; v++) pf[v] = X4[gofs[v]];

    float acc0 = 0.f, acc1 = 0.f, acc2 = 0.f, acc3 = 0.f, nj = 0.f;
    const int jb  = tid * 32;
    const int jsw = tid & 31;

    #pragma unroll
    for (int t = 0; t < 4; t++) {
        __syncthreads();                 // buffer free from previous readers
        #pragma unroll
        for (int v = 0; v < 8; v++) {
            const int rb = sbase[v] & ~127;        // r*32
            const int fb = sbase[v] & 127;         // 4*f (within row, pre-xor)
            const int k  = skey[v];
            sX[rb + ((fb + 0) ^ k)] = pf[v].x;
            sX[rb + ((fb + 1) ^ k)] = pf[v].y;
            sX[rb + ((fb + 2) ^ k)] = pf[v].z;
            sX[rb + ((fb + 3) ^ k)] = pf[v].w;
        }
        __syncthreads();                 // tile visible

        if (t < 3) {                     // prefetch next tile (hides LDG)
            #pragma unroll
            for (int v = 0; v < 8; v++) pf[v] = X4[gofs[v] + (t + 1) * 8];
        }

        // compute: thread j reads its own row, conflict-free LDS.32
        #pragma unroll
        for (int c4 = 0; c4 < 8; c4++) {
            const float4 a0 = sA4[0][t * 8 + c4];   // broadcast LDS.128
            const float4 a1 = sA4[1][t * 8 + c4];
            const float4 a2 = sA4[2][t * 8 + c4];
            const float4 a3 = sA4[3][t * 8 + c4];
            const int cb = 4 * c4;
            {   const float xv = sX[jb + ((cb + 0) ^ jsw)];
                acc0 += xv * a0.x; acc1 += xv * a1.x;
                acc2 += xv * a2.x; acc3 += xv * a3.x; nj += xv * xv; }
            {   const float xv = sX[jb + ((cb + 1) ^ jsw)];
                acc0 += xv * a0.y; acc1 += xv * a1.y;
                acc2 += xv * a2.y; acc3 += xv * a3.y; nj += xv * xv; }
            {   const float xv = sX[jb + ((cb + 2) ^ jsw)];
                acc0 += xv * a0.z; acc1 += xv * a1.z;
                acc2 += xv * a2.z; acc3 += xv * a3.z; nj += xv * xv; }
            {   const float xv = sX[jb + ((cb + 3) ^ jsw)];
                acc0 += xv * a0.w; acc1 += xv * a1.w;
                acc2 += xv * a2.w; acc3 += xv * a3.w; nj += xv * xv; }
        }
    }

    // anchor norms: the owning thread's nj IS the anchor norm
    const int da = tid - i0;
    if (da >= 0 && da < APB) sna[da] = nj;
    __syncthreads();

    float dist[APB];
    dist[0] = sqrtf(fmaxf(sna[0] + nj - 2.0f * acc0, 0.0f));
    dist[1] = sqrtf(fmaxf(sna[1] + nj - 2.0f * acc1, 0.0f));
    dist[2] = sqrtf(fmaxf(sna[2] + nj - 2.0f * acc2, 0.0f));
    dist[3] = sqrtf(fmaxf(sna[3] + nj - 2.0f * acc3, 0.0f));

    // ---- positive compaction per anchor (few smem atomics; classes ~10 wide)
    const int j  = tid;
    const int lj = slbl[j];
    float dn[APB];
    #pragma unroll
    for (int a = 0; a < APB; a++) {
        const int la = slbl[i0 + a];               // broadcast LDS
        const bool isPos = (lj == la) && (j != i0 + a);
        if (isPos) {
            const int s = atomicAdd(&npos[a], 1);
            if (s < 64) posA[a][s] = dist[a] + MARGIN;
        }
        dn[a] = (lj != la) ? dist[a] : CUDART_INF_F;  // masked -> relu & cnt 0
    }
    __syncthreads();

    // ---- triplet accumulation: thread j is the negative; loop positives
    float lsum = 0.0f;
    int   lcnt = 0;
    #pragma unroll
    for (int a = 0; a < APB; a++) {
        int np = npos[a];
        if (np > 64) np = 64;
        const float dneg = dn[a];
        for (int p = 0; p < np; p++) {
            const float t = posA[a][p] - dneg;      // broadcast LDS
            if (t > 0.0f)    lsum += t;
            if (t > 1e-16f)  lcnt += 1;
        }
    }

    // ---- block reduce (16 warps)
    #pragma unroll
    for (int o = 16; o > 0; o >>= 1) {
        lsum += __shfl_xor_sync(0xffffffffu, lsum, o);
        lcnt += __shfl_xor_sync(0xffffffffu, lcnt, o);
    }
    if (lane == 0) { wsum[warp] = lsum; wcnt[warp] = lcnt; }
    __syncthreads();

    if (warp == 0) {
        float s = (lane < 16) ? wsum[lane] : 0.0f;
        int   c = (lane < 16) ? wcnt[lane] : 0;
        #pragma unroll
        for (int o = 8; o > 0; o >>= 1) {
            s += __shfl_xor_sync(0xffffffffu, s, o);
            c += __shfl_xor_sync(0xffffffffu, c, o);
        }
        if (lane == 0) {
            atomicAdd(&g_sum, (double)s);
            atomicAdd(&g_cnt, c);
            __threadfence();
            const unsigned ticket = atomicAdd(&g_done, 1u);
            if (ticket == (unsigned)(NBLK - 1)) {
                const double S = atomicAdd(&g_sum, 0.0);
                const int    C = atomicAdd(&g_cnt, 0);
                out[0] = (float)(S / ((double)C + 1e-16));
                // reset for next graph replay (all blocks done with globals)
                g_sum  = 0.0;
                g_cnt  = 0;
                g_done = 0u;
            }
        }
    }
}

extern "C" void kernel_launch(void* const* d_in, const int* in_sizes, int n_in,
                              void* d_out, int out_size) {
    const float* X      = (const float*)d_in[0];   // [512, 128] fp32
    const int*   labels = (const int*)d_in[1];     // [512] int32
    float*       out    = (float*)d_out;           // scalar fp32

    cudaFuncSetAttribute(triplet_onekernel,
                         cudaFuncAttributeMaxDynamicSharedMemorySize, SMEM_DYN);
    triplet_onekernel<<<NBLK, TPB, SMEM_DYN>>>(X, labels, out);
}

// round 14
// speedup vs baseline: 1.0043x; 1.0043x over previous
#include <cuda_runtime.h>
#include <math_constants.h>

#define N 512
#define D 128
#define MARGIN 0.3f
#define APB 4            // anchors per block
#define NBLK (N / APB)   // 128 blocks = one wave (1 block/SM)
#define TPB 512          // thread t owns row j = t
#define NF4 (D / 4)      // 32 float4 per row
#define RS 9             // padded row stride in float4 (36 words ≡ 4 mod 32)
#define BUFSZ (N * RS)   // 4608 float4 per buffer
#define SMEM_DYN (2 * BUFSZ * 16)   // 144 KB, double-buffered

__device__ double       g_sum  = 0.0;
__device__ int          g_cnt  = 0;
__device__ unsigned int g_done = 0u;

__global__ __launch_bounds__(TPB)
void triplet_onekernel(const float* __restrict__ X,
                       const int* __restrict__ labels,
                       float* __restrict__ out)
{
    // sX4[buf][r*RS + f]: padded stride-9 float4 rows. Phase-level bank math:
    // STS.128 (8 lanes share r, f=0..7) and LDS.128 (8 consecutive j, fixed f)
    // both hit 8 distinct 4-bank groups -> conflict-free, no XOR needed.
    extern __shared__ __align__(16) float4 sX4[];

    __shared__ float4 sA4[APB][NF4];   // 4 anchor rows
    __shared__ float  sna[APB];        // anchor squared norms
    __shared__ int    slbl[N];
    __shared__ int    npos[APB];
    __shared__ float  posA[APB][64];
    __shared__ float  wsum[16];
    __shared__ int    wcnt[16];

    const int tid  = threadIdx.x;
    const int lane = tid & 31;
    const int warp = tid >> 5;
    const int i0   = blockIdx.x * APB;

    slbl[tid] = labels[tid];
    if (tid < APB) npos[tid] = 0;

    // anchors -> smem (warp a loads anchor a; one float4 per lane)
    if (warp < APB)
        sA4[warp][lane] = ((const float4*)(X + (i0 + warp) * D))[lane];

    // Staging geometry: idx = v*512 + tid; r = idx>>3, f = idx&7.
    // 8 consecutive lanes share r -> one 128B line per group (coalesced LDG.128).
    const float4* __restrict__ X4 = (const float4*)X;
    int gofs[8], so4[8];
    #pragma unroll
    for (int v = 0; v < 8; v++) {
        const int idx = v * TPB + tid;
        const int r = idx >> 3, f = idx & 7;
        gofs[v] = r * NF4 + f;           // + t*8 per tile
        so4[v]  = r * RS + f;            // padded smem slot (float4 units)
    }

    // tile 0: load + store into buffer 0
    float4 pf[8];
    #pragma unroll
    for (int v = 0; v < 8; v++) pf[v] = X4[gofs[v]];
    #pragma unroll
    for (int v = 0; v < 8; v++) sX4[so4[v]] = pf[v];
    __syncthreads();

    float acc0 = 0.f, acc1 = 0.f, acc2 = 0.f, acc3 = 0.f, nj = 0.f;
    const int jb = tid * RS;
    int pbase = 0;

    #pragma unroll
    for (int t = 0; t < 4; t++) {
        if (t < 3) {                       // prefetch next tile (hidden by FMA)
            #pragma unroll
            for (int v = 0; v < 8; v++) pf[v] = X4[gofs[v] + (t + 1) * 8];
        }

        // compute: thread j reads its own row via conflict-free LDS.128
        #pragma unroll
        for (int c4 = 0; c4 < 8; c4++) {
            const float4 xv = sX4[pbase + jb + c4];
            const float4 a0 = sA4[0][t * 8 + c4];   // broadcast LDS.128
            const float4 a1 = sA4[1][t * 8 + c4];
            const float4 a2 = sA4[2][t * 8 + c4];
            const float4 a3 = sA4[3][t * 8 + c4];
            acc0 += xv.x * a0.x + xv.y * a0.y + xv.z * a0.z + xv.w * a0.w;
            acc1 += xv.x * a1.x + xv.y * a1.y + xv.z * a1.z + xv.w * a1.w;
            acc2 += xv.x * a2.x + xv.y * a2.y + xv.z * a2.z + xv.w * a2.w;
            acc3 += xv.x * a3.x + xv.y * a3.y + xv.z * a3.z + xv.w * a3.w;
            nj   += xv.x * xv.x + xv.y * xv.y + xv.z * xv.z + xv.w * xv.w;
        }

        if (t < 3) {                       // write next tile into other buffer
            const int nb = BUFSZ - pbase;
            #pragma unroll
            for (int v = 0; v < 8; v++) sX4[nb + so4[v]] = pf[v];
            __syncthreads();               // separates read(t) epoch from write(t+2)
            pbase = nb;
        }
    }

    // anchor norms: the owning thread's nj IS the anchor norm
    const int da = tid - i0;
    if (da >= 0 && da < APB) sna[da] = nj;
    __syncthreads();

    float dist[APB];
    dist[0] = sqrtf(fmaxf(sna[0] + nj - 2.0f * acc0, 0.0f));
    dist[1] = sqrtf(fmaxf(sna[1] + nj - 2.0f * acc1, 0.0f));
    dist[2] = sqrtf(fmaxf(sna[2] + nj - 2.0f * acc2, 0.0f));
    dist[3] = sqrtf(fmaxf(sna[3] + nj - 2.0f * acc3, 0.0f));

    // ---- positive compaction per anchor (few smem atomics; classes ~10 wide)
    const int j  = tid;
    const int lj = slbl[j];
    float dn[APB];
    #pragma unroll
    for (int a = 0; a < APB; a++) {
        const int la = slbl[i0 + a];               // broadcast LDS
        const bool isPos = (lj == la) && (j != i0 + a);
        if (isPos) {
            const int s = atomicAdd(&npos[a], 1);
            if (s < 64) posA[a][s] = dist[a] + MARGIN;
        }
        dn[a] = (lj != la) ? dist[a] : CUDART_INF_F;  // masked -> relu & cnt 0
    }
    __syncthreads();

    // ---- triplet accumulation: thread j is the negative; loop positives
    float lsum = 0.0f;
    int   lcnt = 0;
    #pragma unroll
    for (int a = 0; a < APB; a++) {
        int np = npos[a];
        if (np > 64) np = 64;
        const float dneg = dn[a];
        for (int p = 0; p < np; p++) {
            const float t = posA[a][p] - dneg;      // broadcast LDS
            if (t > 0.0f)    lsum += t;
            if (t > 1e-16f)  lcnt += 1;
        }
    }

    // ---- block reduce (16 warps)
    #pragma unroll
    for (int o = 16; o > 0; o >>= 1) {
        lsum += __shfl_xor_sync(0xffffffffu, lsum, o);
        lcnt += __shfl_xor_sync(0xffffffffu, lcnt, o);
    }
    if (lane == 0) { wsum[warp] = lsum; wcnt[warp] = lcnt; }
    __syncthreads();

    if (warp == 0) {
        float s = (lane < 16) ? wsum[lane] : 0.0f;
        int   c = (lane < 16) ? wcnt[lane] : 0;
        #pragma unroll
        for (int o = 8; o > 0; o >>= 1) {
            s += __shfl_xor_sync(0xffffffffu, s, o);
            c += __shfl_xor_sync(0xffffffffu, c, o);
        }
        if (lane == 0) {
            atomicAdd(&g_sum, (double)s);
            atomicAdd(&g_cnt, c);
            __threadfence();
            const unsigned ticket = atomicAdd(&g_done, 1u);
            if (ticket == (unsigned)(NBLK - 1)) {
                const double S = atomicAdd(&g_sum, 0.0);
                const int    C = atomicAdd(&g_cnt, 0);
                out[0] = (float)(S / ((double)C + 1e-16));
                // reset for next graph replay (all blocks done with globals)
                g_sum  = 0.0;
                g_cnt  = 0;
                g_done = 0u;
            }
        }
    }
}

extern "C" void kernel_launch(void* const* d_in, const int* in_sizes, int n_in,
                              void* d_out, int out_size) {
    const float* X      = (const float*)d_in[0];   // [512, 128] fp32
    const int*   labels = (const int*)d_in[1];     // [512] int32
    float*       out    = (float*)d_out;           // scalar fp32

    cudaFuncSetAttribute(triplet_onekernel,
                         cudaFuncAttributeMaxDynamicSharedMemorySize, SMEM_DYN);
    triplet_onekernel<<<NBLK, TPB, SMEM_DYN>>>(X, labels, out);
}